// round 9
// baseline (speedup 1.0000x reference)
#include <cuda_runtime.h>

// Problem constants
#define Bb   2
#define Nn   2048
#define Ee   2048
#define Hh   16
#define Gg   4
#define HKVn 4
#define Dd   128

// Scratch (device globals: allocation-free per harness rules)
__device__ float g_q[(size_t)Bb * Hh * Nn * Dd];    // [b*H+h][n][d]
__device__ float g_k[(size_t)Bb * HKVn * Nn * Dd];  // [b*HKV+h][n][d]
__device__ float g_v[(size_t)Bb * HKVn * Nn * Dd];
__device__ float g_o[(size_t)Bb * Nn * Ee];         // [b][n][E]

// ---------------------------------------------------------------------------
// GEMM: C[i,j] = sum_e A[i,e] * W[j,e]   (A row-major MxK, W row-major NxK)
// mode 0: A=x, N=3072 combined (q|k|v), scatter epilogue into g_q/g_k/g_v
// mode 1: A=g_o, W0=Wo, C=out row-major
// Register prefetch (R3) + smem ping-pong (R7): 1 barrier per K-tile.
// ---------------------------------------------------------------------------
#define BM 128
#define BN 128
#define BK 16
#define TP 132   // padded tile stride

__global__ void __launch_bounds__(256) gemm_kernel(
    const float* __restrict__ A,
    const float* __restrict__ W0,
    const float* __restrict__ W1,
    const float* __restrict__ W2,
    float* __restrict__ C,
    int mode)
{
    const int K = Ee;
    __shared__ float As[2][BK][TP];
    __shared__ float Bs[2][BK][TP];

    int tid = threadIdx.x;
    int tx = tid & 15, ty = tid >> 4;
    int row0 = blockIdx.y * BM;
    int col0 = blockIdx.x * BN;

    const float* Bp;
    if (mode == 0) {
        if (col0 < 2048)      Bp = W0 + (size_t)col0 * K;
        else if (col0 < 2560) Bp = W1 + (size_t)(col0 - 2048) * K;
        else                  Bp = W2 + (size_t)(col0 - 2560) * K;
    } else {
        Bp = W0 + (size_t)col0 * K;
    }

    // Per-thread tile-load coordinates (2 float4 for A, 2 for B)
    int lr[2], lc[2];
    #pragma unroll
    for (int it = 0; it < 2; ++it) {
        int l = tid + it * 256;
        lr[it] = l >> 2;          // row within 128-row tile
        lc[it] = (l & 3) * 4;     // k-offset within BK (float index)
    }

    float acc[8][8];
    #pragma unroll
    for (int i = 0; i < 8; i++)
        #pragma unroll
        for (int j = 0; j < 8; j++) acc[i][j] = 0.f;

    // Preload first tile into registers
    float4 avr[2], bvr[2];
    #pragma unroll
    for (int it = 0; it < 2; ++it) {
        avr[it] = *reinterpret_cast<const float4*>(
            A + (size_t)(row0 + lr[it]) * K + lc[it]);
        bvr[it] = *reinterpret_cast<const float4*>(
            Bp + (size_t)lr[it] * K + lc[it]);
    }

    int buf = 0;
    for (int k0 = 0; k0 < K; k0 += BK, buf ^= 1) {
        // Commit staged registers to smem buffer `buf`
        #pragma unroll
        for (int it = 0; it < 2; ++it) {
            int r = lr[it], c = lc[it];
            As[buf][c + 0][r] = avr[it].x; As[buf][c + 1][r] = avr[it].y;
            As[buf][c + 2][r] = avr[it].z; As[buf][c + 3][r] = avr[it].w;
            Bs[buf][c + 0][r] = bvr[it].x; Bs[buf][c + 1][r] = bvr[it].y;
            Bs[buf][c + 2][r] = bvr[it].z; Bs[buf][c + 3][r] = bvr[it].w;
        }
        __syncthreads();

        // Prefetch next tile (LDGs overlap the FFMA loop below)
        if (k0 + BK < K) {
            int kn = k0 + BK;
            #pragma unroll
            for (int it = 0; it < 2; ++it) {
                avr[it] = *reinterpret_cast<const float4*>(
                    A + (size_t)(row0 + lr[it]) * K + kn + lc[it]);
                bvr[it] = *reinterpret_cast<const float4*>(
                    Bp + (size_t)lr[it] * K + kn + lc[it]);
            }
        }

        #pragma unroll
        for (int kk = 0; kk < BK; kk++) {
            float4 a0 = *reinterpret_cast<float4*>(&As[buf][kk][ty * 4]);
            float4 a1 = *reinterpret_cast<float4*>(&As[buf][kk][64 + ty * 4]);
            float4 b0 = *reinterpret_cast<float4*>(&Bs[buf][kk][tx * 4]);
            float4 b1 = *reinterpret_cast<float4*>(&Bs[buf][kk][64 + tx * 4]);
            float ar[8] = {a0.x, a0.y, a0.z, a0.w, a1.x, a1.y, a1.z, a1.w};
            float br[8] = {b0.x, b0.y, b0.z, b0.w, b1.x, b1.y, b1.z, b1.w};
            #pragma unroll
            for (int i = 0; i < 8; i++)
                #pragma unroll
                for (int j = 0; j < 8; j++)
                    acc[i][j] += ar[i] * br[j];
        }
        // no trailing barrier: next iteration writes the other buffer
    }

    // Epilogue
    int rl[8], cl[8];
    #pragma unroll
    for (int t = 0; t < 4; t++) {
        rl[t] = ty * 4 + t;  rl[4 + t] = 64 + ty * 4 + t;
        cl[t] = tx * 4 + t;  cl[4 + t] = 64 + tx * 4 + t;
    }
    #pragma unroll
    for (int i = 0; i < 8; i++) {
        int r = row0 + rl[i];
        #pragma unroll
        for (int j = 0; j < 8; j++) {
            int cg = col0 + cl[j];
            float val = acc[i][j];
            if (mode == 1) {
                C[(size_t)r * Ee + cg] = val;
            } else {
                int b = r >> 11, n = r & 2047;
                if (cg < 2048) {
                    int h = cg >> 7, d = cg & 127;
                    g_q[((size_t)(b * Hh + h) * Nn + n) * Dd + d] = val;
                } else if (cg < 2560) {
                    int c2 = cg - 2048; int h = c2 >> 7, d = c2 & 127;
                    g_k[((size_t)(b * HKVn + h) * Nn + n) * Dd + d] = val;
                } else {
                    int c2 = cg - 2560; int h = c2 >> 7, d = c2 & 127;
                    g_v[((size_t)(b * HKVn + h) * Nn + n) * Dd + d] = val;
                }
            }
        }
    }
}

// ---------------------------------------------------------------------------
// Flash attention, fp32.  grid=(B*H, N/TQ), block=256 (16x16 threads)
// 64 queries x 2048 keys in 64-key tiles, online softmax in registers.
// K/V smem ping-pong removes the trailing barrier; the softmax->PV barrier is
// a __syncwarp (Ss row r=ty*4+i is produced and consumed by the same 16 lanes
// of one warp). 1 block barrier per tile.
// ---------------------------------------------------------------------------
#define TQ 64
#define TK 64
#define SQP 132   // Qs/Ks row stride (float4-aligned rows)
#define SSP 68    // Ss row stride (float4-aligned)

__global__ void __launch_bounds__(256, 1) attn_kernel()
{
    extern __shared__ float sm[];
    float* Qs  = sm;                        // TQ x SQP
    float* Ks0 = Qs  + TQ * SQP;            // TK x SQP (buf 0)
    float* Ks1 = Ks0 + TK * SQP;            // TK x SQP (buf 1)
    float* Vs0 = Ks1 + TK * SQP;            // TK x Dd  (buf 0)
    float* Vs1 = Vs0 + TK * Dd;             // TK x Dd  (buf 1)
    float* Ss  = Vs1 + TK * Dd;             // TQ x SSP (holds P)

    int tid = threadIdx.x;
    int tx = tid & 15, ty = tid >> 4;
    int bh = blockIdx.x;
    int b = bh >> 4, h = bh & 15;
    int hkv = h >> 2;                 // group size 4
    int q0 = blockIdx.y * TQ;

    const float* qg = g_q + ((size_t)bh * Nn + q0) * Dd;
    const float* kg = g_k + (size_t)(b * HKVn + hkv) * Nn * Dd;
    const float* vg = g_v + (size_t)(b * HKVn + hkv) * Nn * Dd;

    // Per-thread K/V load coordinates (8 float4 each per tile)
    int lrr[8], lcc[8];
    #pragma unroll
    for (int it = 0; it < 8; ++it) {
        int l = tid + it * 256;
        lrr[it] = l >> 5;         // row within 64-row tile
        lcc[it] = (l & 31) * 4;   // d-offset (float index)
    }

    // Load Q tile (64x128): vector STS
    #pragma unroll
    for (int it = 0; it < 8; ++it) {
        float4 v = *reinterpret_cast<const float4*>(
            qg + (size_t)lrr[it] * Dd + lcc[it]);
        *reinterpret_cast<float4*>(&Qs[lrr[it] * SQP + lcc[it]]) = v;
    }

    // Preload first K/V tile into registers
    float4 kvr[8], vvr[8];
    #pragma unroll
    for (int it = 0; it < 8; ++it) {
        kvr[it] = *reinterpret_cast<const float4*>(
            kg + (size_t)lrr[it] * Dd + lcc[it]);
        vvr[it] = *reinterpret_cast<const float4*>(
            vg + (size_t)lrr[it] * Dd + lcc[it]);
    }
    __syncthreads();

    // Per-thread online-softmax state, replicated across the 16 tx lanes.
    float m[4], lsum[4];
    #pragma unroll
    for (int i = 0; i < 4; i++) { m[i] = -1e30f; lsum[i] = 0.f; }

    float o[4][8];
    #pragma unroll
    for (int i = 0; i < 4; i++)
        #pragma unroll
        for (int j = 0; j < 8; j++) o[i][j] = 0.f;

    const float scale = 0.08838834764831845f;  // 1/sqrt(128)

    for (int kt = 0; kt < Nn / TK; ++kt) {
        float* Ks = (kt & 1) ? Ks1 : Ks0;
        float* Vs = (kt & 1) ? Vs1 : Vs0;

        // Commit staged K/V registers to this iteration's buffers
        #pragma unroll
        for (int it = 0; it < 8; ++it) {
            *reinterpret_cast<float4*>(&Ks[lrr[it] * SQP + lcc[it]]) = kvr[it];
            *reinterpret_cast<float4*>(&Vs[lrr[it] * Dd + lcc[it]]) = vvr[it];
        }
        __syncthreads();   // the only block barrier in the loop

        // Prefetch next K/V tile (LDGs overlap S + softmax + PV below)
        if (kt + 1 < Nn / TK) {
            const float* kpn = kg + (size_t)(kt + 1) * TK * Dd;
            const float* vpn = vg + (size_t)(kt + 1) * TK * Dd;
            #pragma unroll
            for (int it = 0; it < 8; ++it) {
                kvr[it] = *reinterpret_cast<const float4*>(
                    kpn + (size_t)lrr[it] * Dd + lcc[it]);
                vvr[it] = *reinterpret_cast<const float4*>(
                    vpn + (size_t)lrr[it] * Dd + lcc[it]);
            }
        }

        // S = Q K^T tile: each thread 4q x 4k, float4 over kk
        float s[4][4];
        #pragma unroll
        for (int i = 0; i < 4; i++)
            #pragma unroll
            for (int j = 0; j < 4; j++) s[i][j] = 0.f;

        #pragma unroll 8
        for (int kk = 0; kk < Dd; kk += 4) {
            float4 qv[4], kv[4];
            #pragma unroll
            for (int i = 0; i < 4; i++)
                qv[i] = *reinterpret_cast<const float4*>(&Qs[(ty * 4 + i) * SQP + kk]);
            #pragma unroll
            for (int j = 0; j < 4; j++)
                kv[j] = *reinterpret_cast<const float4*>(&Ks[(tx * 4 + j) * SQP + kk]);
            #pragma unroll
            for (int i = 0; i < 4; i++)
                #pragma unroll
                for (int j = 0; j < 4; j++) {
                    s[i][j] += qv[i].x * kv[j].x;
                    s[i][j] += qv[i].y * kv[j].y;
                    s[i][j] += qv[i].z * kv[j].z;
                    s[i][j] += qv[i].w * kv[j].w;
                }
        }

        // Register online softmax per row (16-lane shuffle groups)
        #pragma unroll
        for (int i = 0; i < 4; i++) {
            float mx = fmaxf(fmaxf(s[i][0], s[i][1]), fmaxf(s[i][2], s[i][3])) * scale;
            #pragma unroll
            for (int off = 1; off < 16; off <<= 1)
                mx = fmaxf(mx, __shfl_xor_sync(0xffffffffu, mx, off));
            float mnew = fmaxf(m[i], mx);
            float alpha = __expf(m[i] - mnew);
            float p0 = __expf(s[i][0] * scale - mnew);
            float p1 = __expf(s[i][1] * scale - mnew);
            float p2 = __expf(s[i][2] * scale - mnew);
            float p3 = __expf(s[i][3] * scale - mnew);
            float sum = (p0 + p1) + (p2 + p3);
            #pragma unroll
            for (int off = 1; off < 16; off <<= 1)
                sum += __shfl_xor_sync(0xffffffffu, sum, off);
            lsum[i] = lsum[i] * alpha + sum;
            m[i] = mnew;
            #pragma unroll
            for (int j = 0; j < 8; j++) o[i][j] *= alpha;
            *reinterpret_cast<float4*>(&Ss[(ty * 4 + i) * SSP + tx * 4]) =
                make_float4(p0, p1, p2, p3);
        }
        // Ss rows are produced and consumed within one warp's 16-lane group.
        __syncwarp();

        // O += P @ V  (each thread 4q x 8d)
        #pragma unroll 2
        for (int k = 0; k < TK; k++) {
            float4 v0 = *reinterpret_cast<const float4*>(&Vs[k * Dd + tx * 8]);
            float4 v1 = *reinterpret_cast<const float4*>(&Vs[k * Dd + tx * 8 + 4]);
            #pragma unroll
            for (int i = 0; i < 4; i++) {
                float p = Ss[(ty * 4 + i) * SSP + k];
                o[i][0] += p * v0.x; o[i][1] += p * v0.y;
                o[i][2] += p * v0.z; o[i][3] += p * v0.w;
                o[i][4] += p * v1.x; o[i][5] += p * v1.y;
                o[i][6] += p * v1.z; o[i][7] += p * v1.w;
            }
        }
        // no trailing barrier: next iteration writes the other K/V buffers,
        // and Ss is warp-local (rewritten only by the same lanes that read it).
    }

    // Normalize and write O to [b][n][h*128+d]
    #pragma unroll
    for (int i = 0; i < 4; i++) {
        int r = ty * 4 + i;
        float inv = 1.f / lsum[i];
        int nIdx = q0 + r;
        float* dst = g_o + ((size_t)b * Nn + nIdx) * Ee + h * Dd + tx * 8;
        float4 w0 = make_float4(o[i][0] * inv, o[i][1] * inv, o[i][2] * inv, o[i][3] * inv);
        float4 w1 = make_float4(o[i][4] * inv, o[i][5] * inv, o[i][6] * inv, o[i][7] * inv);
        *reinterpret_cast<float4*>(dst) = w0;
        *reinterpret_cast<float4*>(dst + 4) = w1;
    }
}

// ---------------------------------------------------------------------------
extern "C" void kernel_launch(void* const* d_in, const int* in_sizes, int n_in,
                              void* d_out, int out_size)
{
    const float* x  = (const float*)d_in[0];
    const float* Wq = (const float*)d_in[1];
    const float* Wk = (const float*)d_in[2];
    const float* Wv = (const float*)d_in[3];
    const float* Wo = (const float*)d_in[4];
    float* out = (float*)d_out;

    size_t smem_attn = (size_t)(TQ * SQP + 2 * TK * SQP + 2 * TK * Dd
                                + TQ * SSP) * sizeof(float);
    cudaFuncSetAttribute(attn_kernel, cudaFuncAttributeMaxDynamicSharedMemorySize,
                         (int)smem_attn);

    float* gA = nullptr;
    cudaGetSymbolAddress((void**)&gA, g_o);

    // 1) fused QKV projection: M=4096, N=3072 (q|k|v), K=2048
    gemm_kernel<<<dim3(24, 32), 256>>>(x, Wq, Wk, Wv, nullptr, 0);
    // 2) GQA flash attention
    attn_kernel<<<dim3(Bb * Hh, Nn / TQ), 256, smem_attn>>>();
    // 3) output projection: M=4096, N=2048, K=2048
    gemm_kernel<<<dim3(16, 32), 256>>>(gA, Wo, nullptr, nullptr, out, 1);
}

// round 15
// speedup vs baseline: 1.1851x; 1.1851x over previous
#include <cuda_runtime.h>
#include <cuda_bf16.h>
#include <mma.h>
#include <cstdint>

using namespace nvcuda;

// Problem constants
#define Bb   2
#define Nn   2048
#define Ee   2048
#define Hh   16
#define Gg   4
#define HKVn 4
#define Dd   128

// fp32 scratch (attention inputs)
__device__ float g_q[(size_t)Bb * Hh * Nn * Dd];
__device__ float g_k[(size_t)Bb * HKVn * Nn * Dd];
__device__ float g_v[(size_t)Bb * HKVn * Nn * Dd];

// bf16 split scratch
__device__ __nv_bfloat16 gx_hi[(size_t)4096 * 2048];
__device__ __nv_bfloat16 gx_lo[(size_t)4096 * 2048];
__device__ __nv_bfloat16 gw3_hi[(size_t)3072 * 2048];   // Wq|Wk|Wv rows
__device__ __nv_bfloat16 gw3_lo[(size_t)3072 * 2048];
__device__ __nv_bfloat16 gwo_hi[(size_t)2048 * 2048];
__device__ __nv_bfloat16 gwo_lo[(size_t)2048 * 2048];
__device__ __nv_bfloat16 go_hi[(size_t)4096 * 2048];    // attention output (split)
__device__ __nv_bfloat16 go_lo[(size_t)4096 * 2048];

// ---------------------------------------------------------------------------
// Split conversion: hi = bf16(x), lo = bf16(x - hi)
// ---------------------------------------------------------------------------
__global__ void __launch_bounds__(256) split_kernel(
    const float* __restrict__ src, __nv_bfloat16* __restrict__ hi,
    __nv_bfloat16* __restrict__ lo, int n4)
{
    int i = blockIdx.x * 256 + threadIdx.x;
    if (i >= n4) return;
    float4 v = reinterpret_cast<const float4*>(src)[i];
    __nv_bfloat16 h0 = __float2bfloat16(v.x), h1 = __float2bfloat16(v.y);
    __nv_bfloat16 h2 = __float2bfloat16(v.z), h3 = __float2bfloat16(v.w);
    __nv_bfloat16 l0 = __float2bfloat16(v.x - __bfloat162float(h0));
    __nv_bfloat16 l1 = __float2bfloat16(v.y - __bfloat162float(h1));
    __nv_bfloat16 l2 = __float2bfloat16(v.z - __bfloat162float(h2));
    __nv_bfloat16 l3 = __float2bfloat16(v.w - __bfloat162float(h3));
    reinterpret_cast<__nv_bfloat162*>(hi)[2 * i]     = __nv_bfloat162(h0, h1);
    reinterpret_cast<__nv_bfloat162*>(hi)[2 * i + 1] = __nv_bfloat162(h2, h3);
    reinterpret_cast<__nv_bfloat162*>(lo)[2 * i]     = __nv_bfloat162(l0, l1);
    reinterpret_cast<__nv_bfloat162*>(lo)[2 * i + 1] = __nv_bfloat162(l2, l3);
}

// ---------------------------------------------------------------------------
// Split-bf16 wmma GEMM: C[i,j] = sum_e A[i,e]*W[j,e].
// CTA: 128x128 tile, 256 threads = 8 warps (2 x 4), 64x32 per warp.
// K chunks of 32; per k-step (16): acc += Ah*Bh + Ah*Bl + Al*Bh.
// mode 1: C row-major with ldc.  mode 0: scatter tiles into g_q/g_k/g_v
// (every 16x16 tile is within one (b, head) block: rows 16-aligned and
//  2048 % 16 == 0, cols 16-aligned within 128-aligned head boundaries).
// ---------------------------------------------------------------------------
#define GBK 32
#define SAP 40   // smem stride (bf16 elements), mult of 8 for wmma ldm

__global__ void __launch_bounds__(256) mma_gemm_kernel(
    const __nv_bfloat16* __restrict__ Ahi, const __nv_bfloat16* __restrict__ Alo,
    const __nv_bfloat16* __restrict__ Bhi, const __nv_bfloat16* __restrict__ Blo,
    float* __restrict__ C, int ldc, int mode)
{
    __shared__ __nv_bfloat16 Ah[128][SAP], Al[128][SAP];
    __shared__ __nv_bfloat16 Bh[128][SAP], Bl[128][SAP];

    const int K = Ee;
    int tid = threadIdx.x;
    int wid = tid >> 5;
    int wm = wid >> 2, wn = wid & 3;          // 2 x 4 warp grid
    int row0 = blockIdx.y * 128;
    int col0 = blockIdx.x * 128;

    // Per-thread chunk-load coords: 2 uint4 (16 bf16) per matrix per chunk
    int lr[2], lc[2];
    #pragma unroll
    for (int it = 0; it < 2; ++it) {
        int l = tid + it * 256;
        lr[it] = l >> 2;          // row 0..127
        lc[it] = (l & 3) * 8;     // col 0,8,16,24
    }

    wmma::fragment<wmma::accumulator, 16, 16, 16, float> acc[4][2];
    #pragma unroll
    for (int i = 0; i < 4; ++i)
        #pragma unroll
        for (int j = 0; j < 2; ++j) wmma::fill_fragment(acc[i][j], 0.0f);

    // Preload first chunk
    uint4 sAh[2], sAl[2], sBh[2], sBl[2];
    #pragma unroll
    for (int it = 0; it < 2; ++it) {
        size_t oa = (size_t)(row0 + lr[it]) * K + lc[it];
        size_t ob = (size_t)(col0 + lr[it]) * K + lc[it];
        sAh[it] = *reinterpret_cast<const uint4*>(Ahi + oa);
        sAl[it] = *reinterpret_cast<const uint4*>(Alo + oa);
        sBh[it] = *reinterpret_cast<const uint4*>(Bhi + ob);
        sBl[it] = *reinterpret_cast<const uint4*>(Blo + ob);
    }

    for (int k0 = 0; k0 < K; k0 += GBK) {
        #pragma unroll
        for (int it = 0; it < 2; ++it) {
            *reinterpret_cast<uint4*>(&Ah[lr[it]][lc[it]]) = sAh[it];
            *reinterpret_cast<uint4*>(&Al[lr[it]][lc[it]]) = sAl[it];
            *reinterpret_cast<uint4*>(&Bh[lr[it]][lc[it]]) = sBh[it];
            *reinterpret_cast<uint4*>(&Bl[lr[it]][lc[it]]) = sBl[it];
        }
        __syncthreads();

        if (k0 + GBK < K) {
            int kn = k0 + GBK;
            #pragma unroll
            for (int it = 0; it < 2; ++it) {
                size_t oa = (size_t)(row0 + lr[it]) * K + kn + lc[it];
                size_t ob = (size_t)(col0 + lr[it]) * K + kn + lc[it];
                sAh[it] = *reinterpret_cast<const uint4*>(Ahi + oa);
                sAl[it] = *reinterpret_cast<const uint4*>(Alo + oa);
                sBh[it] = *reinterpret_cast<const uint4*>(Bhi + ob);
                sBl[it] = *reinterpret_cast<const uint4*>(Blo + ob);
            }
        }

        #pragma unroll
        for (int ks = 0; ks < 2; ++ks) {
            wmma::fragment<wmma::matrix_a, 16, 16, 16, __nv_bfloat16, wmma::row_major> fah[4], fal[4];
            wmma::fragment<wmma::matrix_b, 16, 16, 16, __nv_bfloat16, wmma::col_major> fbh[2], fbl[2];
            #pragma unroll
            for (int i = 0; i < 4; ++i) {
                wmma::load_matrix_sync(fah[i], &Ah[wm * 64 + i * 16][ks * 16], SAP);
                wmma::load_matrix_sync(fal[i], &Al[wm * 64 + i * 16][ks * 16], SAP);
            }
            #pragma unroll
            for (int j = 0; j < 2; ++j) {
                wmma::load_matrix_sync(fbh[j], &Bh[wn * 32 + j * 16][ks * 16], SAP);
                wmma::load_matrix_sync(fbl[j], &Bl[wn * 32 + j * 16][ks * 16], SAP);
            }
            #pragma unroll
            for (int i = 0; i < 4; ++i)
                #pragma unroll
                for (int j = 0; j < 2; ++j) {
                    wmma::mma_sync(acc[i][j], fah[i], fbh[j], acc[i][j]);
                    wmma::mma_sync(acc[i][j], fah[i], fbl[j], acc[i][j]);
                    wmma::mma_sync(acc[i][j], fal[i], fbh[j], acc[i][j]);
                }
        }
        __syncthreads();
    }

    // Epilogue
    #pragma unroll
    for (int i = 0; i < 4; ++i)
        #pragma unroll
        for (int j = 0; j < 2; ++j) {
            int gr0 = row0 + wm * 64 + i * 16;          // 16-aligned
            int cg0 = col0 + wn * 32 + j * 16;          // 16-aligned
            if (mode == 1) {
                float* dst = C + (size_t)gr0 * ldc + cg0;
                wmma::store_matrix_sync(dst, acc[i][j], ldc, wmma::mem_row_major);
            } else {
                int b = gr0 >> 11, n0 = gr0 & 2047;     // tile rows share b
                float* dst;
                if (cg0 < 2048) {
                    int h = cg0 >> 7, d0 = cg0 & 127;
                    dst = &g_q[((size_t)(b * Hh + h) * Nn + n0) * Dd + d0];
                } else if (cg0 < 2560) {
                    int c2 = cg0 - 2048; int h = c2 >> 7, d0 = c2 & 127;
                    dst = &g_k[((size_t)(b * HKVn + h) * Nn + n0) * Dd + d0];
                } else {
                    int c2 = cg0 - 2560; int h = c2 >> 7, d0 = c2 & 127;
                    dst = &g_v[((size_t)(b * HKVn + h) * Nn + n0) * Dd + d0];
                }
                wmma::store_matrix_sync(dst, acc[i][j], Dd, wmma::mem_row_major);
            }
        }
}

// ---------------------------------------------------------------------------
// Flash attention, fp32 (verified R8/R9 core). Epilogue fused with the hi/lo
// split: writes go_hi/go_lo directly (numerically identical to storing fp32
// then running split_kernel on it).
// ---------------------------------------------------------------------------
#define TQ 64
#define TK 64
#define SQP 132
#define SSP 68

__global__ void __launch_bounds__(256, 1) attn_kernel()
{
    extern __shared__ float sm[];
    float* Qs  = sm;
    float* Ks0 = Qs  + TQ * SQP;
    float* Ks1 = Ks0 + TK * SQP;
    float* Vs0 = Ks1 + TK * SQP;
    float* Vs1 = Vs0 + TK * Dd;
    float* Ss  = Vs1 + TK * Dd;

    int tid = threadIdx.x;
    int tx = tid & 15, ty = tid >> 4;
    int bh = blockIdx.x;
    int b = bh >> 4, h = bh & 15;
    int hkv = h >> 2;
    int q0 = blockIdx.y * TQ;

    const float* qg = g_q + ((size_t)bh * Nn + q0) * Dd;
    const float* kg = g_k + (size_t)(b * HKVn + hkv) * Nn * Dd;
    const float* vg = g_v + (size_t)(b * HKVn + hkv) * Nn * Dd;

    int lrr[8], lcc[8];
    #pragma unroll
    for (int it = 0; it < 8; ++it) {
        int l = tid + it * 256;
        lrr[it] = l >> 5;
        lcc[it] = (l & 31) * 4;
    }

    #pragma unroll
    for (int it = 0; it < 8; ++it) {
        float4 v = *reinterpret_cast<const float4*>(qg + (size_t)lrr[it] * Dd + lcc[it]);
        *reinterpret_cast<float4*>(&Qs[lrr[it] * SQP + lcc[it]]) = v;
    }

    float4 kvr[8], vvr[8];
    #pragma unroll
    for (int it = 0; it < 8; ++it) {
        kvr[it] = *reinterpret_cast<const float4*>(kg + (size_t)lrr[it] * Dd + lcc[it]);
        vvr[it] = *reinterpret_cast<const float4*>(vg + (size_t)lrr[it] * Dd + lcc[it]);
    }
    __syncthreads();

    float m[4], lsum[4];
    #pragma unroll
    for (int i = 0; i < 4; i++) { m[i] = -1e30f; lsum[i] = 0.f; }
    float o[4][8];
    #pragma unroll
    for (int i = 0; i < 4; i++)
        #pragma unroll
        for (int j = 0; j < 8; j++) o[i][j] = 0.f;

    const float scale = 0.08838834764831845f;

    for (int kt = 0; kt < Nn / TK; ++kt) {
        float* Ks = (kt & 1) ? Ks1 : Ks0;
        float* Vs = (kt & 1) ? Vs1 : Vs0;

        #pragma unroll
        for (int it = 0; it < 8; ++it) {
            *reinterpret_cast<float4*>(&Ks[lrr[it] * SQP + lcc[it]]) = kvr[it];
            *reinterpret_cast<float4*>(&Vs[lrr[it] * Dd + lcc[it]]) = vvr[it];
        }
        __syncthreads();

        if (kt + 1 < Nn / TK) {
            const float* kpn = kg + (size_t)(kt + 1) * TK * Dd;
            const float* vpn = vg + (size_t)(kt + 1) * TK * Dd;
            #pragma unroll
            for (int it = 0; it < 8; ++it) {
                kvr[it] = *reinterpret_cast<const float4*>(kpn + (size_t)lrr[it] * Dd + lcc[it]);
                vvr[it] = *reinterpret_cast<const float4*>(vpn + (size_t)lrr[it] * Dd + lcc[it]);
            }
        }

        float s[4][4];
        #pragma unroll
        for (int i = 0; i < 4; i++)
            #pragma unroll
            for (int j = 0; j < 4; j++) s[i][j] = 0.f;

        #pragma unroll 8
        for (int kk = 0; kk < Dd; kk += 4) {
            float4 qv[4], kv[4];
            #pragma unroll
            for (int i = 0; i < 4; i++)
                qv[i] = *reinterpret_cast<const float4*>(&Qs[(ty * 4 + i) * SQP + kk]);
            #pragma unroll
            for (int j = 0; j < 4; j++)
                kv[j] = *reinterpret_cast<const float4*>(&Ks[(tx * 4 + j) * SQP + kk]);
            #pragma unroll
            for (int i = 0; i < 4; i++)
                #pragma unroll
                for (int j = 0; j < 4; j++) {
                    s[i][j] += qv[i].x * kv[j].x;
                    s[i][j] += qv[i].y * kv[j].y;
                    s[i][j] += qv[i].z * kv[j].z;
                    s[i][j] += qv[i].w * kv[j].w;
                }
        }

        #pragma unroll
        for (int i = 0; i < 4; i++) {
            float mx = fmaxf(fmaxf(s[i][0], s[i][1]), fmaxf(s[i][2], s[i][3])) * scale;
            #pragma unroll
            for (int off = 1; off < 16; off <<= 1)
                mx = fmaxf(mx, __shfl_xor_sync(0xffffffffu, mx, off));
            float mnew = fmaxf(m[i], mx);
            float alpha = __expf(m[i] - mnew);
            float p0 = __expf(s[i][0] * scale - mnew);
            float p1 = __expf(s[i][1] * scale - mnew);
            float p2 = __expf(s[i][2] * scale - mnew);
            float p3 = __expf(s[i][3] * scale - mnew);
            float sum = (p0 + p1) + (p2 + p3);
            #pragma unroll
            for (int off = 1; off < 16; off <<= 1)
                sum += __shfl_xor_sync(0xffffffffu, sum, off);
            lsum[i] = lsum[i] * alpha + sum;
            m[i] = mnew;
            #pragma unroll
            for (int j = 0; j < 8; j++) o[i][j] *= alpha;
            *reinterpret_cast<float4*>(&Ss[(ty * 4 + i) * SSP + tx * 4]) =
                make_float4(p0, p1, p2, p3);
        }
        __syncwarp();

        #pragma unroll 2
        for (int k = 0; k < TK; k++) {
            float4 v0 = *reinterpret_cast<const float4*>(&Vs[k * Dd + tx * 8]);
            float4 v1 = *reinterpret_cast<const float4*>(&Vs[k * Dd + tx * 8 + 4]);
            #pragma unroll
            for (int i = 0; i < 4; i++) {
                float p = Ss[(ty * 4 + i) * SSP + k];
                o[i][0] += p * v0.x; o[i][1] += p * v0.y;
                o[i][2] += p * v0.z; o[i][3] += p * v0.w;
                o[i][4] += p * v1.x; o[i][5] += p * v1.y;
                o[i][6] += p * v1.z; o[i][7] += p * v1.w;
            }
        }
    }

    // Normalize, split to hi/lo, and write bf16 outputs for the out-proj GEMM.
    #pragma unroll
    for (int i = 0; i < 4; i++) {
        float inv = 1.f / lsum[i];
        int nIdx = q0 + ty * 4 + i;
        size_t off = ((size_t)b * Nn + nIdx) * Ee + h * Dd + tx * 8;
        __nv_bfloat162 hv[4], lv[4];
        #pragma unroll
        for (int j2 = 0; j2 < 4; ++j2) {
            float a = o[i][j2 * 2] * inv;
            float c = o[i][j2 * 2 + 1] * inv;
            __nv_bfloat16 ha = __float2bfloat16(a);
            __nv_bfloat16 hc = __float2bfloat16(c);
            hv[j2] = __nv_bfloat162(ha, hc);
            lv[j2] = __nv_bfloat162(__float2bfloat16(a - __bfloat162float(ha)),
                                    __float2bfloat16(c - __bfloat162float(hc)));
        }
        *reinterpret_cast<uint4*>(go_hi + off) = *reinterpret_cast<uint4*>(hv);
        *reinterpret_cast<uint4*>(go_lo + off) = *reinterpret_cast<uint4*>(lv);
    }
}

// ---------------------------------------------------------------------------
extern "C" void kernel_launch(void* const* d_in, const int* in_sizes, int n_in,
                              void* d_out, int out_size)
{
    const float* x  = (const float*)d_in[0];
    const float* Wq = (const float*)d_in[1];
    const float* Wk = (const float*)d_in[2];
    const float* Wv = (const float*)d_in[3];
    const float* Wo = (const float*)d_in[4];
    float* out = (float*)d_out;

    size_t smem_attn = (size_t)(TQ * SQP + 2 * TK * SQP + 2 * TK * Dd + TQ * SSP)
                       * sizeof(float);
    cudaFuncSetAttribute(attn_kernel, cudaFuncAttributeMaxDynamicSharedMemorySize,
                         (int)smem_attn);

    __nv_bfloat16 *pxh, *pxl, *pw3h, *pw3l, *pwoh, *pwol, *poh, *pol;
    cudaGetSymbolAddress((void**)&pxh, gx_hi);
    cudaGetSymbolAddress((void**)&pxl, gx_lo);
    cudaGetSymbolAddress((void**)&pw3h, gw3_hi);
    cudaGetSymbolAddress((void**)&pw3l, gw3_lo);
    cudaGetSymbolAddress((void**)&pwoh, gwo_hi);
    cudaGetSymbolAddress((void**)&pwol, gwo_lo);
    cudaGetSymbolAddress((void**)&poh, go_hi);
    cudaGetSymbolAddress((void**)&pol, go_lo);

    // 1) split conversions
    split_kernel<<<8192, 256>>>(x, pxh, pxl, 2097152);
    split_kernel<<<4096, 256>>>(Wq, pw3h, pw3l, 1048576);
    split_kernel<<<1024, 256>>>(Wk, pw3h + 4194304, pw3l + 4194304, 262144);
    split_kernel<<<1024, 256>>>(Wv, pw3h + 5242880, pw3l + 5242880, 262144);
    split_kernel<<<4096, 256>>>(Wo, pwoh, pwol, 1048576);

    // 2) QKV projection (wmma split-bf16, fused scatter): M=4096, N=3072, K=2048
    mma_gemm_kernel<<<dim3(24, 32), 256>>>(pxh, pxl, pw3h, pw3l, nullptr, 0, 0);

    // 3) GQA flash attention (fp32 core, fused split epilogue)
    attn_kernel<<<dim3(Bb * Hh, Nn / TQ), 256, smem_attn>>>();

    // 4) out-projection (wmma split-bf16): M=4096, N=2048, K=2048
    mma_gemm_kernel<<<dim3(16, 32), 256>>>(poh, pol, pwoh, pwol, out, 2048, 1);
}